// round 5
// baseline (speedup 1.0000x reference)
#include <cuda_runtime.h>
#include <cuda_fp16.h>
#include <math.h>
#include <stdint.h>

#define NN 100000
#define EE 3200000
#define EA (EE + NN)
#define FIN 78
#define FG 256
#define FH 128

// ---------------- scratch (device globals; no allocation) ----------------
__device__ __half d_mx16[(size_t)NN * 80];    // padded fp16 mol_x
__device__ __half d_hf[(size_t)NN * 256];     // fp16 copy of current h (gather source)
__device__ __half d_agg[(size_t)NN * 512];    // aggregated features (2 heads)
__device__ float d_h [(size_t)NN * 256];
__device__ float d_x [(size_t)NN * 256];
__device__ float d_g [(size_t)NN * 256];
__device__ __half d_xt[(size_t)NN * 128];
__device__ __half d_ef[(size_t)NN * 128];
__device__ float d_hy[(size_t)NN * 128];
__device__ float d_bc[512 * 256];
__device__ float d_cb[256];
__device__ float d_wv[256 * 4];
__device__ float d_asrc[NN * 2];
__device__ float d_adst[NN * 2];
__device__ int csrA_off[NN + 1]; __device__ int csrA_val[EA];
__device__ int csrC_off[NN + 1]; __device__ int csrC_val[EE];
__device__ int cntA[NN], cntC[NN];
__device__ int curA[NN], curC[NN];
__device__ float d_binv[NN], d_dinv[NN];

// ---------------- CSR construction ----------------
__global__ void zero_counts_kernel() {
    int i = blockIdx.x * blockDim.x + threadIdx.x;
    if (i < NN) { cntA[i] = 0; cntC[i] = 0; }
}

__global__ void count_kernel(const int* __restrict__ ei) {
    int i = blockIdx.x * blockDim.x + threadIdx.x;
    if (i >= EE) return;
    int s = ei[i];
    int d = ei[EE + i];
    atomicAdd(&cntA[d], 1);   // edges by dst (self-loop slot added in scan)
    atomicAdd(&cntC[s], 1);   // edges by src
}

// 2 blocks. Block 0: scan (cntA[i]+1) -> csrA_off, write curA, self-loop at
// segment end, binv. Block 1: scan cntC -> csrC_off, curC, dinv.
__global__ void scan2_kernel() {
    bool isA = (blockIdx.x == 0);
    const int* in = isA ? cntA : cntC;
    int* out = isA ? csrA_off : csrC_off;
    const int n = NN;
    __shared__ int wsum[32];
    __shared__ int carry;
    int tid = threadIdx.x, lane = tid & 31, wid = tid >> 5;
    if (tid == 0) carry = 0;
    __syncthreads();
    for (int base = 0; base < n; base += 1024) {
        int i = base + tid;
        int raw = (i < n) ? in[i] : 0;
        int v = raw + (isA ? ((i < n) ? 1 : 0) : 0);
        int x = v;
        #pragma unroll
        for (int d = 1; d < 32; d <<= 1) {
            int y = __shfl_up_sync(0xFFFFFFFFu, x, d);
            if (lane >= d) x += y;
        }
        if (lane == 31) wsum[wid] = x;
        __syncthreads();
        if (wid == 0) {
            int w = wsum[lane];
            #pragma unroll
            for (int d = 1; d < 32; d <<= 1) {
                int y = __shfl_up_sync(0xFFFFFFFFu, w, d);
                if (lane >= d) w += y;
            }
            wsum[lane] = w;
        }
        __syncthreads();
        int excl = carry + (wid ? wsum[wid - 1] : 0) + x - v;
        if (i < n) {
            out[i] = excl;
            if (isA) {
                curA[i] = excl;
                csrA_val[excl + raw] = i;  // self loop pinned at segment end
                d_binv[i] = raw > 0 ? 1.0f / (float)raw : 0.0f;
            } else {
                curC[i] = excl;
                d_dinv[i] = raw > 0 ? 1.0f / (float)raw : 0.0f;
            }
        }
        if (i == n - 1) out[n] = excl + v;
        __syncthreads();
        if (tid == 0) carry += wsum[31];
        __syncthreads();
    }
}

__global__ void fill_kernel(const int* __restrict__ ei) {
    int i = blockIdx.x * blockDim.x + threadIdx.x;
    if (i >= EE) return;
    int s = ei[i];
    int d = ei[EE + i];
    csrA_val[atomicAdd(&curA[d], 1)] = s;
    csrC_val[atomicAdd(&curC[s], 1)] = d;
}

// ---------------- fp16 tensor-core GEMM (m16n8k16, pipelined) ----------------
__device__ __forceinline__ void mma_f16(float* c, const uint32_t* a, uint32_t b0, uint32_t b1) {
    asm volatile(
        "mma.sync.aligned.m16n8k16.row.col.f32.f16.f16.f32 "
        "{%0,%1,%2,%3},{%4,%5,%6,%7},{%8,%9},{%0,%1,%2,%3};"
        : "+f"(c[0]), "+f"(c[1]), "+f"(c[2]), "+f"(c[3])
        : "r"(a[0]), "r"(a[1]), "r"(a[2]), "r"(a[3]), "r"(b0), "r"(b1));
}

#define PA 18
#define TILE_U (128 * PA)

// ASRC: 0 = fp32 (optional concat A2), 2 = fp16 dense
// EPI:  0 = float out (scale+bias+relu, optional half copy), 1 = half out,
//       2 = gate blend -> float h_new + half copy
template <int ASRC, int EPI>
__global__ __launch_bounds__(256) void gemm_f16_kernel(
    const void* __restrict__ Ap, int lda, int K1,
    const float* __restrict__ A2, int lda2,
    const float* __restrict__ B1, const float* __restrict__ B2, int ldb,
    int SP, int KV1, int KV2,
    float* __restrict__ C, __half* __restrict__ Chalf,
    int M, int N, int Ktot,
    const float* __restrict__ bias, int relu, float scale,
    const float* __restrict__ molb)
{
    __shared__ uint32_t Asm[2 * TILE_U];
    __shared__ uint32_t Bsm[2 * TILE_U];
    int tid = threadIdx.x;
    int lane = tid & 31, wid = tid >> 5;
    int wm = wid & 3, wn = wid >> 2;
    int row0 = blockIdx.y * 128, col0 = blockIdx.x * 128;
    int g = lane >> 2, tg = lane & 3;

    float acc[2][8][4];
    #pragma unroll
    for (int mi = 0; mi < 2; mi++)
        #pragma unroll
        for (int ni = 0; ni < 8; ni++)
            #pragma unroll
            for (int q = 0; q < 4; q++) acc[mi][ni][q] = 0.0f;

    const float* Af = (const float*)Ap;
    const __half* Ah = (const __half*)Ap;

    float4 raf[4];
    uint2 rah[4];
    float4 rb[4];

    auto loadA = [&](int k0) {
        #pragma unroll
        for (int i = 0; i < 4; i++) {
            int l4 = tid + i * 256;
            int r = l4 >> 3, c4 = (l4 & 7) << 2;
            int grow = row0 + r, gk = k0 + c4;
            if (ASRC == 2) {
                uint2 u = make_uint2(0u, 0u);
                if (grow < M) u = *(const uint2*)(Ah + (size_t)grow * lda + gk);
                rah[i] = u;
            } else {
                float4 v = make_float4(0.f, 0.f, 0.f, 0.f);
                if (grow < M) {
                    if (gk + 3 < K1) {
                        v = *(const float4*)(Af + (size_t)grow * lda + gk);
                    } else {
                        float* pv = &v.x;
                        #pragma unroll
                        for (int j = 0; j < 4; j++) {
                            int kk = gk + j;
                            float x = 0.0f;
                            if (kk < K1) x = Af[(size_t)grow * lda + kk];
                            else if (kk < Ktot) x = A2[(size_t)grow * lda2 + (kk - K1)];
                            pv[j] = x;
                        }
                    }
                }
                raf[i] = v;
            }
        }
    };
    auto storeA = [&](uint32_t* As) {
        #pragma unroll
        for (int i = 0; i < 4; i++) {
            int l4 = tid + i * 256;
            int r = l4 >> 3, c2 = (l4 & 7) << 1;
            if (ASRC == 2) {
                As[r * PA + c2] = rah[i].x;
                As[r * PA + c2 + 1] = rah[i].y;
            } else {
                __half2 h0 = __floats2half2_rn(raf[i].x, raf[i].y);
                __half2 h1 = __floats2half2_rn(raf[i].z, raf[i].w);
                As[r * PA + c2] = *(uint32_t*)&h0;
                As[r * PA + c2 + 1] = *(uint32_t*)&h1;
            }
        }
    };
    auto loadB = [&](int k0) {
        #pragma unroll
        for (int i = 0; i < 4; i++) {
            int l4 = tid + i * 256;
            int k = l4 >> 5, n4 = (l4 & 31) << 2;
            int kk = k0 + k;
            float4 v = make_float4(0.f, 0.f, 0.f, 0.f);
            if (kk < SP) {
                if (kk < KV1) v = *(const float4*)(B1 + (size_t)kk * ldb + col0 + n4);
            } else if (kk < Ktot) {
                int j = kk - SP;
                if (j < KV2) v = *(const float4*)(B2 + (size_t)j * ldb + col0 + n4);
            }
            rb[i] = v;
        }
    };
    auto storeB = [&](uint32_t* Bs) {
        __half* BsH = (__half*)Bs;
        #pragma unroll
        for (int i = 0; i < 4; i++) {
            int l4 = tid + i * 256;
            int k = l4 >> 5, n4 = (l4 & 31) << 2;
            BsH[(n4 + 0) * (2 * PA) + k] = __float2half_rn(rb[i].x);
            BsH[(n4 + 1) * (2 * PA) + k] = __float2half_rn(rb[i].y);
            BsH[(n4 + 2) * (2 * PA) + k] = __float2half_rn(rb[i].z);
            BsH[(n4 + 3) * (2 * PA) + k] = __float2half_rn(rb[i].w);
        }
    };

    int T = (Ktot + 31) >> 5;
    loadA(0); loadB(0);
    storeA(Asm); storeB(Bsm);
    __syncthreads();

    for (int t = 0; t < T; t++) {
        int buf = t & 1;
        bool more = (t + 1 < T);
        if (more) { loadA((t + 1) << 5); loadB((t + 1) << 5); }
        const uint32_t* As = Asm + buf * TILE_U;
        const uint32_t* Bs = Bsm + buf * TILE_U;
        #pragma unroll
        for (int ks = 0; ks < 2; ks++) {
            uint32_t af[2][4];
            #pragma unroll
            for (int mi = 0; mi < 2; mi++) {
                int r = wm * 32 + mi * 16 + g;
                int c = ks * 8 + tg;
                af[mi][0] = As[r * PA + c];
                af[mi][1] = As[(r + 8) * PA + c];
                af[mi][2] = As[r * PA + c + 4];
                af[mi][3] = As[(r + 8) * PA + c + 4];
            }
            #pragma unroll
            for (int ni = 0; ni < 8; ni++) {
                int n = wn * 64 + ni * 8 + g;
                uint32_t b0 = Bs[n * PA + ks * 8 + tg];
                uint32_t b1 = Bs[n * PA + ks * 8 + tg + 4];
                mma_f16(acc[0][ni], af[0], b0, b1);
                mma_f16(acc[1][ni], af[1], b0, b1);
            }
        }
        if (more) {
            storeA(Asm + (buf ^ 1) * TILE_U);
            storeB(Bsm + (buf ^ 1) * TILE_U);
        }
        __syncthreads();
    }

    // epilogue
    #pragma unroll
    for (int mi = 0; mi < 2; mi++) {
        int r0 = row0 + wm * 32 + mi * 16 + g;
        #pragma unroll
        for (int ni = 0; ni < 8; ni++) {
            int c = col0 + wn * 64 + ni * 8 + tg * 2;
            float v0 = acc[mi][ni][0], v1 = acc[mi][ni][1];
            float v2 = acc[mi][ni][2], v3 = acc[mi][ni][3];
            if (EPI == 0) {
                float b0v = bias ? bias[c] : 0.0f;
                float b1v = bias ? bias[c + 1] : 0.0f;
                v0 = v0 * scale + b0v; v1 = v1 * scale + b1v;
                v2 = v2 * scale + b0v; v3 = v3 * scale + b1v;
                if (relu) {
                    v0 = fmaxf(v0, 0.f); v1 = fmaxf(v1, 0.f);
                    v2 = fmaxf(v2, 0.f); v3 = fmaxf(v3, 0.f);
                }
                if (r0 < M) {
                    *(float2*)(C + (size_t)r0 * N + c) = make_float2(v0, v1);
                    if (Chalf) *(__half2*)(Chalf + (size_t)r0 * N + c) = __floats2half2_rn(v0, v1);
                }
                if (r0 + 8 < M) {
                    *(float2*)(C + (size_t)(r0 + 8) * N + c) = make_float2(v2, v3);
                    if (Chalf) *(__half2*)(Chalf + (size_t)(r0 + 8) * N + c) = __floats2half2_rn(v2, v3);
                }
            } else if (EPI == 1) {
                if (r0 < M) *(__half2*)(Chalf + (size_t)r0 * N + c) = __floats2half2_rn(v0, v1);
                if (r0 + 8 < M) *(__half2*)(Chalf + (size_t)(r0 + 8) * N + c) = __floats2half2_rn(v2, v3);
            } else {
                const float* Af2 = (const float*)Ap;
                float cb0 = bias[c] + molb[c];
                float cb1 = bias[c + 1] + molb[c + 1];
                #pragma unroll
                for (int half_ = 0; half_ < 2; half_++) {
                    int r = r0 + half_ * 8;
                    if (r >= M) continue;
                    float va = half_ ? v2 : v0, vb = half_ ? v3 : v1;
                    float z0 = 1.0f / (1.0f + __expf(-(va + cb0)));
                    float z1 = 1.0f / (1.0f + __expf(-(vb + cb1)));
                    float x0 = Af2[(size_t)r * lda + c], x1 = Af2[(size_t)r * lda + c + 1];
                    float h0 = A2[(size_t)r * lda2 + c], h1 = A2[(size_t)r * lda2 + c + 1];
                    float o0 = z0 * x0 + (1.0f - z0) * h0;
                    float o1 = z1 * x1 + (1.0f - z1) * h1;
                    *(float2*)(C + (size_t)r * N + c) = make_float2(o0, o1);
                    *(__half2*)(Chalf + (size_t)r * N + c) = __floats2half2_rn(o0, o1);
                }
            }
        }
    }
}

template <int ASRC, int EPI>
static void run_gemm(const void* A, int lda, int K1, const float* A2, int lda2,
                     const float* B1, const float* B2, int ldb, int SP, int KV1, int KV2,
                     float* C, __half* Chalf, int M, int N, int Ktot,
                     const float* bias, int relu, float scale, const float* molb) {
    dim3 grid(N / 128, (M + 127) / 128);
    gemm_f16_kernel<ASRC, EPI><<<grid, 256>>>(
        A, lda, K1, A2, lda2, B1, B2, ldb, SP, KV1, KV2,
        C, Chalf, M, N, Ktot, bias, relu, scale, molb);
}

// fused gate weight Bc[512][256] = [fc1^T ; fc2^T], combined bias
__global__ void build_bc_kernel(const float* __restrict__ fc1w, const float* __restrict__ fc2w,
                                const float* __restrict__ fc1b, const float* __restrict__ fc2b) {
    int idx = blockIdx.x * blockDim.x + threadIdx.x;
    if (idx >= 512 * 256) return;
    int k = idx >> 8, n = idx & 255;
    d_bc[idx] = (k < 256) ? fc1w[n * 256 + k] : fc2w[n * 256 + (k - 256)];
    if (idx < 256) d_cb[idx] = fc1b[idx] + fc2b[idx];
}

// mol_x -> padded fp16 [N][80]
__global__ void conv_mx_kernel(const float* __restrict__ x) {
    int idx = blockIdx.x * blockDim.x + threadIdx.x;
    if (idx >= NN * 40) return;
    int n = idx / 40, c2 = idx % 40;
    float a = 0.f, b = 0.f;
    int c = c2 * 2;
    if (c < FIN) a = x[(size_t)n * FIN + c];
    if (c + 1 < FIN) b = x[(size_t)n * FIN + c + 1];
    ((__half2*)d_mx16)[idx] = __floats2half2_rn(a, b);
}

// ---------------- exact attention logits ----------------
__global__ void build_wv_kernel(const float* __restrict__ W, const float* __restrict__ as,
                                const float* __restrict__ ad) {
    int k = blockIdx.x, t = threadIdx.x;
    float w0 = W[(size_t)k * 512 + t], w1 = W[(size_t)k * 512 + 256 + t];
    float p0 = w0 * as[t], p1 = w1 * as[256 + t];
    float p2 = w0 * ad[t], p3 = w1 * ad[256 + t];
    __shared__ float red[8][4];
    int lane = t & 31, wid = t >> 5;
    #pragma unroll
    for (int d = 16; d; d >>= 1) {
        p0 += __shfl_down_sync(0xFFFFFFFFu, p0, d);
        p1 += __shfl_down_sync(0xFFFFFFFFu, p1, d);
        p2 += __shfl_down_sync(0xFFFFFFFFu, p2, d);
        p3 += __shfl_down_sync(0xFFFFFFFFu, p3, d);
    }
    if (lane == 0) { red[wid][0] = p0; red[wid][1] = p1; red[wid][2] = p2; red[wid][3] = p3; }
    __syncthreads();
    if (t == 0) {
        float r0 = 0, r1 = 0, r2 = 0, r3 = 0;
        #pragma unroll
        for (int w = 0; w < 8; w++) { r0 += red[w][0]; r1 += red[w][1]; r2 += red[w][2]; r3 += red[w][3]; }
        d_wv[k * 4 + 0] = r0; d_wv[k * 4 + 1] = r1; d_wv[k * 4 + 2] = r2; d_wv[k * 4 + 3] = r3;
    }
}

__global__ void attn2_kernel(const float* __restrict__ x, int K) {
    int warp = threadIdx.x >> 5, lane = threadIdx.x & 31;
    int n = blockIdx.x * 4 + warp;
    if (n >= NN) return;
    const float* xr = x + (size_t)n * K;
    float s0 = 0, s1 = 0, s2 = 0, s3 = 0;
    for (int c = lane; c < K; c += 32) {
        float xv = xr[c];
        float4 wv = ((const float4*)d_wv)[c];
        s0 += xv * wv.x; s1 += xv * wv.y; s2 += xv * wv.z; s3 += xv * wv.w;
    }
    #pragma unroll
    for (int d = 16; d; d >>= 1) {
        s0 += __shfl_down_sync(0xFFFFFFFFu, s0, d);
        s1 += __shfl_down_sync(0xFFFFFFFFu, s1, d);
        s2 += __shfl_down_sync(0xFFFFFFFFu, s2, d);
        s3 += __shfl_down_sync(0xFFFFFFFFu, s3, d);
    }
    if (lane == 0) {
        d_asrc[n * 2] = s0; d_asrc[n * 2 + 1] = s1;
        d_adst[n * 2] = s2; d_adst[n * 2 + 1] = s3;
    }
}

__device__ __forceinline__ float lrelu02(float v) { return v >= 0.0f ? v : 0.2f * v; }

// ---------------- fused online-softmax GAT aggregate ----------------
// One block per node. CH2 = active half2 columns of the source row.
// BLOCK threads; chunk of BLOCK edges: compute logits -> block max ->
// rescale accumulators -> accumulate p_j * x_src.
template <int BLOCK, int CH2, int NW>
__global__ void gat_fused_kernel(const __half2* __restrict__ src, int ldh2,
                                 __half2* __restrict__ agg, int lda2) {
    int n = blockIdx.x;
    int t = threadIdx.x;
    int lane = t & 31, wid = t >> 5;
    int s0 = csrA_off[n], s1 = csrA_off[n + 1];
    float2 adst = ((const float2*)d_adst)[n];

    __shared__ int ssrc[BLOCK];
    __shared__ float sp0[BLOCK], sp1[BLOCK];
    __shared__ float rm0[NW], rm1[NW];

    float m0 = -1e30f, m1 = -1e30f;
    float sum0 = 0.f, sum1 = 0.f;
    float a0x = 0.f, a0y = 0.f, a1x = 0.f, a1y = 0.f;
    bool act = t < CH2;

    for (int base = s0; base < s1; base += BLOCK) {
        int cnt = min(BLOCK, s1 - base);
        __syncthreads();
        float er0 = -1e30f, er1 = -1e30f;
        if (t < cnt) {
            int sidx = csrA_val[base + t];
            ssrc[t] = sidx;
            float2 as = ((const float2*)d_asrc)[sidx];
            er0 = lrelu02(as.x + adst.x);
            er1 = lrelu02(as.y + adst.y);
        }
        // block max
        float e0 = er0, e1 = er1;
        #pragma unroll
        for (int d = 16; d; d >>= 1) {
            e0 = fmaxf(e0, __shfl_xor_sync(0xFFFFFFFFu, e0, d));
            e1 = fmaxf(e1, __shfl_xor_sync(0xFFFFFFFFu, e1, d));
        }
        if (lane == 0) { rm0[wid] = e0; rm1[wid] = e1; }
        __syncthreads();
        float cm0 = rm0[0], cm1 = rm1[0];
        #pragma unroll
        for (int w = 1; w < NW; w++) { cm0 = fmaxf(cm0, rm0[w]); cm1 = fmaxf(cm1, rm1[w]); }
        float nm0 = fmaxf(m0, cm0), nm1 = fmaxf(m1, cm1);
        float f0 = __expf(m0 - nm0), f1 = __expf(m1 - nm1);
        a0x *= f0; a0y *= f0; a1x *= f1; a1y *= f1;
        sum0 *= f0; sum1 *= f1;
        m0 = nm0; m1 = nm1;
        if (t < cnt) {
            sp0[t] = __expf(er0 - nm0);
            sp1[t] = __expf(er1 - nm1);
        }
        __syncthreads();
        if (act) {
            for (int j = 0; j < cnt; j++) {
                float p0 = sp0[j], p1 = sp1[j];
                sum0 += p0; sum1 += p1;
                float2 f = __half22float2(src[(size_t)ssrc[j] * ldh2 + t]);
                a0x += p0 * f.x; a0y += p0 * f.y;
                a1x += p1 * f.x; a1y += p1 * f.y;
            }
        } else {
            for (int j = 0; j < cnt; j++) { sum0 += sp0[j]; sum1 += sp1[j]; }
        }
    }
    if (act) {
        float r0 = 1.0f / sum0, r1 = 1.0f / sum1;
        agg[(size_t)n * lda2 + t] = __floats2half2_rn(a0x * r0, a0y * r0);
        agg[(size_t)n * lda2 + CH2 + t] = __floats2half2_rn(a1x * r1, a1y * r1);
    }
}

// ---------------- hypergraph ----------------
// which=0: group by dst via csrA (skip self at segment end), scale binv
// which=1: group by src via csrC, scale dinv
template <bool OUTH>
__global__ void hyper_gather_kernel(const __half2* __restrict__ in, void* __restrict__ outp,
                                    const float* __restrict__ bias, int which, int relu) {
    const int* off = which ? csrC_off : csrA_off;
    const int* val = which ? csrC_val : csrA_val;
    int n = blockIdx.x;
    int t = threadIdx.x;  // 64
    int s0 = off[n], s1 = off[n + 1];
    if (!which) s1 -= 1;  // csrA segment ends with the self loop: skip it
    float ax = 0, ay = 0;
    __shared__ int sv[64];
    for (int base = s0; base < s1; base += 64) {
        int cnt = min(64, s1 - base);
        __syncthreads();
        if (t < cnt) sv[t] = val[base + t];
        __syncthreads();
        #pragma unroll 4
        for (int j = 0; j < cnt; j++) {
            float2 f = __half22float2(in[(size_t)sv[j] * 64 + t]);
            ax += f.x; ay += f.y;
        }
    }
    float inv = which ? d_dinv[n] : d_binv[n];
    ax *= inv; ay *= inv;
    if (bias) { ax += bias[t * 2]; ay += bias[t * 2 + 1]; }
    if (relu) { ax = fmaxf(ax, 0.f); ay = fmaxf(ay, 0.f); }
    if (OUTH) ((__half2*)outp)[(size_t)n * 64 + t] = __floats2half2_rn(ax, ay);
    else ((float2*)outp)[(size_t)n * 64 + t] = make_float2(ax, ay);
}

__global__ void output_kernel(const float* __restrict__ h, const float* __restrict__ hy,
                              float* __restrict__ out) {
    size_t i = (size_t)blockIdx.x * blockDim.x + threadIdx.x;
    if (i >= (size_t)NN * 384) return;
    int n = (int)(i / 384);
    int c = (int)(i % 384);
    out[i] = (c < 256) ? h[(size_t)n * 256 + c] : hy[(size_t)n * FH + (c - 256)];
}

// ---------------- host side ----------------
extern "C" void kernel_launch(void* const* d_in, const int* in_sizes, int n_in,
                              void* d_out, int out_size) {
    const float* mol_x = (const float*)d_in[0];
    const int*   ei    = (const int*)d_in[1];
    const float* W1 = (const float*)d_in[3];
    const float* as1 = (const float*)d_in[4];
    const float* ad1 = (const float*)d_in[5];
    const float* b1 = (const float*)d_in[6];
    const float* W2 = (const float*)d_in[7];
    const float* as2 = (const float*)d_in[8];
    const float* ad2 = (const float*)d_in[9];
    const float* b2 = (const float*)d_in[10];
    const float* W3 = (const float*)d_in[11];
    const float* as3 = (const float*)d_in[12];
    const float* ad3 = (const float*)d_in[13];
    const float* b3 = (const float*)d_in[14];
    const float* fc1_w = (const float*)d_in[15];
    const float* fc1_b = (const float*)d_in[16];
    const float* fc2_w = (const float*)d_in[17];
    const float* fc2_b = (const float*)d_in[18];
    const float* mol_bias = (const float*)d_in[19];
    const float* theta1 = (const float*)d_in[20];
    const float* hb1 = (const float*)d_in[21];
    const float* theta2 = (const float*)d_in[22];
    const float* hb2 = (const float*)d_in[23];

    __half *p_mx, *p_hf, *p_agg, *p_xt, *p_ef;
    float *p_h, *p_x, *p_g, *p_hy, *p_bc, *p_cb;
    cudaGetSymbolAddress((void**)&p_mx, d_mx16);
    cudaGetSymbolAddress((void**)&p_hf, d_hf);
    cudaGetSymbolAddress((void**)&p_agg, d_agg);
    cudaGetSymbolAddress((void**)&p_h, d_h);
    cudaGetSymbolAddress((void**)&p_x, d_x);
    cudaGetSymbolAddress((void**)&p_g, d_g);
    cudaGetSymbolAddress((void**)&p_xt, d_xt);
    cudaGetSymbolAddress((void**)&p_ef, d_ef);
    cudaGetSymbolAddress((void**)&p_hy, d_hy);
    cudaGetSymbolAddress((void**)&p_bc, d_bc);
    cudaGetSymbolAddress((void**)&p_cb, d_cb);

    // ---- CSR build ----
    zero_counts_kernel<<<(NN + 255) / 256, 256>>>();
    count_kernel<<<(EE + 255) / 256, 256>>>(ei);
    scan2_kernel<<<2, 1024>>>();
    fill_kernel<<<(EE + 255) / 256, 256>>>(ei);

    conv_mx_kernel<<<(NN * 40 + 255) / 256, 256>>>(mol_x);
    build_bc_kernel<<<(512 * 256 + 255) / 256, 256>>>(fc1_w, fc2_w, fc1_b, fc2_b);

    // ---- GAT layer 1 ----
    build_wv_kernel<<<FIN, 256>>>(W1, as1, ad1);
    attn2_kernel<<<(NN + 3) / 4, 128>>>(mol_x, FIN);
    gat_fused_kernel<64, 40, 2><<<NN, 64>>>((const __half2*)p_mx, 40, (__half2*)p_agg, 80);
    run_gemm<2, 0>(p_agg, 160, 160, nullptr, 0, W1, W1 + 256, 512, 80, FIN, FIN,
                   p_h, p_hf, NN, 256, 160, b1, 1, 0.5f, nullptr);

    // ---- GAT layer 2 ----
    build_wv_kernel<<<256, 256>>>(W2, as2, ad2);
    attn2_kernel<<<(NN + 3) / 4, 128>>>(p_h, 256);
    gat_fused_kernel<128, 128, 4><<<NN, 128>>>((const __half2*)p_hf, 128, (__half2*)p_agg, 256);
    run_gemm<2, 0>(p_agg, 512, 512, nullptr, 0, W2, W2 + 256, 512, 256, 256, 256,
                   p_x, nullptr, NN, 256, 512, b2, 1, 0.5f, nullptr);
    run_gemm<0, 2>(p_x, 256, 256, p_h, 256, p_bc, nullptr, 256, 512, 512, 0,
                   p_g, p_hf, NN, 256, 512, p_cb, 0, 1.0f, mol_bias);
    // h (fp32) now in d_g; fp16 copy in d_hf

    // ---- GAT layer 3 ----
    build_wv_kernel<<<256, 256>>>(W3, as3, ad3);
    attn2_kernel<<<(NN + 3) / 4, 128>>>(p_g, 256);
    gat_fused_kernel<128, 128, 4><<<NN, 128>>>((const __half2*)p_hf, 128, (__half2*)p_agg, 256);
    run_gemm<2, 0>(p_agg, 512, 512, nullptr, 0, W3, W3 + 256, 512, 256, 256, 256,
                   p_x, nullptr, NN, 256, 512, b3, 0, 0.5f, nullptr);
    run_gemm<0, 2>(p_x, 256, 256, p_g, 256, p_bc, nullptr, 256, 512, 512, 0,
                   p_h, p_hf, NN, 256, 512, p_cb, 0, 1.0f, mol_bias);
    // final h (fp32) in d_h

    // ---- hypergraph branch ----
    run_gemm<0, 1>(p_h, 256, 256, mol_x, FIN, theta1, nullptr, 128, 334, 334, 0,
                   nullptr, p_xt, NN, 128, 334, nullptr, 0, 1.0f, nullptr);
    hyper_gather_kernel<true ><<<NN, 64>>>((const __half2*)p_xt, p_ef, nullptr, 0, 0);
    hyper_gather_kernel<false><<<NN, 64>>>((const __half2*)p_ef, p_hy, hb1, 1, 1);
    run_gemm<0, 1>(p_hy, 128, 128, nullptr, 0, theta2, nullptr, 128, 128, 128, 0,
                   nullptr, p_xt, NN, 128, 128, nullptr, 0, 1.0f, nullptr);
    hyper_gather_kernel<true ><<<NN, 64>>>((const __half2*)p_xt, p_ef, nullptr, 0, 0);
    hyper_gather_kernel<false><<<NN, 64>>>((const __half2*)p_ef, p_hy, hb2, 1, 1);

    // ---- output: [h | hy] ----
    output_kernel<<<(int)(((size_t)NN * 384 + 255) / 256), 256>>>(p_h, p_hy, (float*)d_out);
}